// round 7
// baseline (speedup 1.0000x reference)
#include <cuda_runtime.h>
#include <float.h>
#include <stdint.h>

#define HID 4096
#define SLOTS 8
#define HEADS 8
#define BD 512
#define HD 64
#define BB 4
#define SS 4096
#define NH 64   // HEADS*SLOTS

// Scratch (no allocations allowed)
__device__ float g_Q[SLOTS * BD];
__device__ float g_Qk[NH * HID];                 // tf32-rounded, scaled by 1/8
__device__ float g_spart[4 * BB * NH * SS];      // split-K score partials
__device__ float g_scores[BB * NH * SS];         // attn probs
__device__ float g_apart[2 * BB * NH * HID];     // split-s agg partials
__device__ float g_mid[BB * SLOTS * BD];
__device__ int   g_sidx[BB * SS];
__device__ int   g_cnt[BB];

#define SPART_SZ (BB * NH * SS)
#define APART_SZ (BB * NH * HID)

__device__ __forceinline__ uint32_t f2tf(float f) {
    uint32_t u;
    asm("cvt.rna.tf32.f32 %0, %1;" : "=r"(u) : "f"(f));
    return u;
}

__device__ __forceinline__ void mma_tf32(float* d, const uint32_t* a, const uint32_t* b) {
    asm volatile(
        "mma.sync.aligned.m16n8k8.row.col.f32.tf32.tf32.f32 "
        "{%0,%1,%2,%3}, {%4,%5,%6,%7}, {%8,%9}, {%0,%1,%2,%3};"
        : "+f"(d[0]), "+f"(d[1]), "+f"(d[2]), "+f"(d[3])
        : "r"(a[0]), "r"(a[1]), "r"(a[2]), "r"(a[3]), "r"(b[0]), "r"(b[1]));
}

__device__ __forceinline__ void cp16(uint32_t smem_dst, const float* gsrc) {
    asm volatile("cp.async.cg.shared.global [%0], [%1], 16;" :: "r"(smem_dst), "l"(gsrc));
}
#define CP_COMMIT asm volatile("cp.async.commit_group;")
#define CP_WAIT1  asm volatile("cp.async.wait_group 1;")

// ---------------------------------------------------------------------------
// 0) compaction + zero g_mid
__global__ void k_compact(const int* __restrict__ mask) {
    __shared__ int tsum[256];
    int b = blockIdx.x, tid = threadIdx.x;
    const int* m = mask + b * SS;
    int loc[16], cnt = 0;
    #pragma unroll
    for (int k = 0; k < 16; k++) {
        loc[k] = (m[tid * 16 + k] != 0);
        cnt += loc[k];
    }
    tsum[tid] = cnt;
    __syncthreads();
    for (int o = 1; o < 256; o <<= 1) {
        int v = (tid >= o) ? tsum[tid - o] : 0;
        __syncthreads();
        tsum[tid] += v;
        __syncthreads();
    }
    int off = tsum[tid] - cnt;
    int total = tsum[255];
    int* out = g_sidx + b * SS;
    #pragma unroll
    for (int k = 0; k < 16; k++)
        if (loc[k]) out[off++] = tid * 16 + k;
    if (tid == 0) {
        g_cnt[b] = total;
        int pad = (total + 31) & ~31;
        for (int i = total; i < pad + 32 && i < SS; i++) out[i] = 0;
    }
    float* gm = g_mid + b * 4096;
    #pragma unroll
    for (int k = 0; k < 16; k++) gm[k * 256 + tid] = 0.f;
}

// ---------------------------------------------------------------------------
// 1) Q = memory_slots @ Wq^T
__global__ void k_qproj(const float* __restrict__ ms, const float* __restrict__ Wq) {
    int warp = (blockIdx.x * blockDim.x + threadIdx.x) >> 5;
    int lane = threadIdx.x & 31;
    if (warp >= SLOTS * BD) return;
    int n = warp / BD, c = warp % BD;
    const float* a = ms + n * HID;
    const float* w = Wq + c * HID;
    float acc = 0.f;
    for (int i = lane; i < HID; i += 32) acc += a[i] * w[i];
    #pragma unroll
    for (int off = 16; off; off >>= 1) acc += __shfl_down_sync(0xffffffffu, acc, off);
    if (lane == 0) g_Q[n * BD + c] = acc;
}

// ---------------------------------------------------------------------------
// 2) Qk (tf32-rounded, /8)
__global__ void k_qk(const float* __restrict__ Wk) {
    __shared__ float qs[HD];
    int j = blockIdx.y;
    int h = j >> 3, n = j & 7;
    if (threadIdx.x < HD) qs[threadIdx.x] = g_Q[n * BD + h * HD + threadIdx.x];
    __syncthreads();
    int i = blockIdx.x * blockDim.x + threadIdx.x;
    float acc = 0.f;
    #pragma unroll 8
    for (int d = 0; d < HD; d++) acc += qs[d] * Wk[(h * HD + d) * HID + i];
    g_Qk[j * HID + i] = __uint_as_float(f2tf(acc * 0.125f));
}

// ---------------------------------------------------------------------------
// 3) scores: CTA tile 64cs x 64j, split-K x4, 2-stage cp.async
#define SA 36
#define S_STAGE (128 * SA)
__global__ void __launch_bounds__(256) k_scores(const float* __restrict__ H) {
    extern __shared__ float sm[];
    int b = blockIdx.y;
    int m0 = blockIdx.x * 64;
    int kc = blockIdx.z;
    int cnt = g_cnt[b];
    if (m0 >= cnt) return;
    int tid = threadIdx.x;
    int lane = tid & 31, w = tid >> 5;
    int wm = w & 1, wn = w >> 1;
    int R = wm * 32, C = wn * 16;
    int ar = lane >> 2, ac = lane & 3;

    uint32_t smem_u32 = (uint32_t)__cvta_generic_to_shared(sm);

    float acc[2][2][4];
    #pragma unroll
    for (int t = 0; t < 2; t++)
        #pragma unroll
        for (int n = 0; n < 2; n++)
            #pragma unroll
            for (int q = 0; q < 4; q++) acc[t][n][q] = 0.f;

    int lra = tid >> 3;
    int lca = (tid & 7) * 4;
    int kbase = kc * (HID / 4);

    const float* rowp[2];
    #pragma unroll
    for (int p = 0; p < 2; p++) {
        int s = g_sidx[b * SS + m0 + p * 32 + lra];
        rowp[p] = H + ((size_t)b * SS + s) * HID + kbase + lca;
    }

    auto issue = [&](int stage, int kt) {
        uint32_t base = smem_u32 + stage * S_STAGE * 4;
        #pragma unroll
        for (int p = 0; p < 2; p++) {
            int r = p * 32 + lra;
            cp16(base + (r * SA + lca) * 4, rowp[p] + kt);
        }
        uint32_t bbase = base + 64 * SA * 4;
        #pragma unroll
        for (int p = 0; p < 2; p++) {
            int r = p * 32 + lra;
            cp16(bbase + (r * SA + lca) * 4, &g_Qk[r * HID + kbase + kt + lca]);
        }
    };

    const int NIT = HID / 4 / 32;   // 32
    issue(0, 0); CP_COMMIT;
    for (int it = 0; it < NIT; it++) {
        if (it + 1 < NIT) issue((it + 1) & 1, (it + 1) * 32);
        CP_COMMIT;
        CP_WAIT1;
        __syncthreads();
        float* As = sm + (it & 1) * S_STAGE;
        float* Bs = As + 64 * SA;
        #pragma unroll
        for (int kk = 0; kk < 32; kk += 8) {
            uint32_t a[2][4], bfrag[2][2];
            #pragma unroll
            for (int t = 0; t < 2; t++) {
                int rb = R + t * 16 + ar;
                a[t][0] = __float_as_uint(As[rb * SA + kk + ac]);
                a[t][1] = __float_as_uint(As[(rb + 8) * SA + kk + ac]);
                a[t][2] = __float_as_uint(As[rb * SA + kk + ac + 4]);
                a[t][3] = __float_as_uint(As[(rb + 8) * SA + kk + ac + 4]);
            }
            #pragma unroll
            for (int n = 0; n < 2; n++) {
                int cb = C + n * 8 + ar;
                bfrag[n][0] = __float_as_uint(Bs[cb * SA + kk + ac]);
                bfrag[n][1] = __float_as_uint(Bs[cb * SA + kk + ac + 4]);
            }
            #pragma unroll
            for (int t = 0; t < 2; t++)
                #pragma unroll
                for (int n = 0; n < 2; n++)
                    mma_tf32(acc[t][n], a[t], bfrag[n]);
        }
        __syncthreads();   // protect buffer (it&1) before next issue overwrites it
    }

    float* Cs = sm;
    #pragma unroll
    for (int t = 0; t < 2; t++) {
        #pragma unroll
        for (int n = 0; n < 2; n++) {
            int row = R + t * 16 + ar;
            int col = C + n * 8 + 2 * ac;
            Cs[col * 65 + row]            = acc[t][n][0];
            Cs[(col + 1) * 65 + row]      = acc[t][n][1];
            Cs[col * 65 + row + 8]        = acc[t][n][2];
            Cs[(col + 1) * 65 + row + 8]  = acc[t][n][3];
        }
    }
    __syncthreads();
    float* dst = g_spart + kc * SPART_SZ;
    #pragma unroll
    for (int l = 0; l < 16; l++) {
        int e = l * 256 + tid;
        int j = e >> 6, m = e & 63;
        dst[((b * NH + j) << 12) + m0 + m] = Cs[j * 65 + m];
    }
}

// ---------------------------------------------------------------------------
// 4) softmax: sum 4 split-K partials, softmax over compacted prefix
__global__ void k_softmax() {
    __shared__ float red[256];
    int row = blockIdx.x;
    int b = row >> 6;
    int cnt = g_cnt[b];
    const float* p0 = g_spart + row * SS;
    float* sc = g_scores + row * SS;
    int tid = threadIdx.x;
    float v[16];
    float mx = -FLT_MAX;
    #pragma unroll
    for (int k = 0; k < 16; k++) {
        int s = k * 256 + tid;
        float val = -FLT_MAX;
        if (s < cnt)
            val = p0[s] + p0[SPART_SZ + s] + p0[2 * SPART_SZ + s] + p0[3 * SPART_SZ + s];
        v[k] = val;
        mx = fmaxf(mx, val);
    }
    red[tid] = mx; __syncthreads();
    for (int o = 128; o; o >>= 1) { if (tid < o) red[tid] = fmaxf(red[tid], red[tid + o]); __syncthreads(); }
    mx = red[0]; __syncthreads();
    float sum = 0.f;
    #pragma unroll
    for (int k = 0; k < 16; k++) { v[k] = __expf(v[k] - mx); sum += v[k]; }
    red[tid] = sum; __syncthreads();
    for (int o = 128; o; o >>= 1) { if (tid < o) red[tid] += red[tid + o]; __syncthreads(); }
    float inv = 1.f / red[0];
    #pragma unroll
    for (int k = 0; k < 16; k++) sc[k * 256 + tid] = __uint_as_float(f2tf(v[k] * inv));
}

// ---------------------------------------------------------------------------
// 5) agg: CTA tile 64j x 64i, split-s x2, 2-stage cp.async
#define SHS 72
#define G_STAGE (64 * SA + 32 * SHS)
__global__ void __launch_bounds__(256) k_agg(const float* __restrict__ H) {
    extern __shared__ float sm[];
    int tid = threadIdx.x;
    int lane = tid & 31, w = tid >> 5;
    int wm = w & 1, wn = w >> 1;
    int R = wm * 32, C = wn * 16;
    int b = blockIdx.y;
    int i0 = blockIdx.x * 64;
    int sc_id = blockIdx.z;
    int ar = lane >> 2, ac = lane & 3;
    int cnt = g_cnt[b];
    int NIT_total = (cnt + 31) >> 5;
    int half = (NIT_total + 1) >> 1;
    int it0 = sc_id * half;
    int it1 = min(NIT_total, it0 + half);

    uint32_t smem_u32 = (uint32_t)__cvta_generic_to_shared(sm);

    float acc[2][2][4];
    #pragma unroll
    for (int t = 0; t < 2; t++)
        #pragma unroll
        for (int n = 0; n < 2; n++)
            #pragma unroll
            for (int q = 0; q < 4; q++) acc[t][n][q] = 0.f;

    const float* Hb = H + (size_t)b * SS * HID;
    const float* A  = g_scores + b * NH * SS;
    const int* sidx = g_sidx + b * SS;

    int lra = tid >> 3;
    int lca = (tid & 7) * 4;
    int hr = tid >> 4;
    int hc = (tid & 15) * 4;

    auto issue = [&](int stage, int it) {
        int st = it * 32;
        uint32_t base = smem_u32 + stage * G_STAGE * 4;
        #pragma unroll
        for (int p = 0; p < 2; p++) {
            int r = p * 32 + lra;
            cp16(base + (r * SA + lca) * 4, &A[r * SS + st + lca]);
        }
        uint32_t hbase = base + 64 * SA * 4;
        #pragma unroll
        for (int p = 0; p < 2; p++) {
            int r = p * 16 + hr;
            int gi = sidx[st + r];
            cp16(hbase + (r * SHS + hc) * 4, &Hb[(size_t)gi * HID + i0 + hc]);
        }
    };

    if (it0 < it1) {
        issue(0, it0); CP_COMMIT;
        for (int it = it0; it < it1; it++) {
            if (it + 1 < it1) issue((it - it0 + 1) & 1, it + 1);
            CP_COMMIT;
            CP_WAIT1;
            __syncthreads();
            float* As = sm + ((it - it0) & 1) * G_STAGE;
            float* Hs = As + 64 * SA;
            #pragma unroll
            for (int kk = 0; kk < 32; kk += 8) {
                uint32_t a[2][4], bfr[2][2];
                #pragma unroll
                for (int t = 0; t < 2; t++) {
                    int rb = R + t * 16 + ar;
                    a[t][0] = __float_as_uint(As[rb * SA + kk + ac]);
                    a[t][1] = __float_as_uint(As[(rb + 8) * SA + kk + ac]);
                    a[t][2] = __float_as_uint(As[rb * SA + kk + ac + 4]);
                    a[t][3] = __float_as_uint(As[(rb + 8) * SA + kk + ac + 4]);
                }
                #pragma unroll
                for (int n = 0; n < 2; n++) {
                    int cb = C + n * 8 + ar;
                    bfr[n][0] = __float_as_uint(Hs[(kk + ac) * SHS + cb]);
                    bfr[n][1] = __float_as_uint(Hs[(kk + ac + 4) * SHS + cb]);
                }
                #pragma unroll
                for (int t = 0; t < 2; t++)
                    #pragma unroll
                    for (int n = 0; n < 2; n++)
                        mma_tf32(acc[t][n], a[t], bfr[n]);
            }
            __syncthreads();
        }
    }

    float* dst = g_apart + sc_id * APART_SZ;
    #pragma unroll
    for (int t = 0; t < 2; t++) {
        #pragma unroll
        for (int n = 0; n < 2; n++) {
            int j = R + t * 16 + ar;
            int i = C + n * 8 + 2 * ac;
            float2 v0 = make_float2(acc[t][n][0], acc[t][n][1]);
            float2 v1 = make_float2(acc[t][n][2], acc[t][n][3]);
            *(float2*)&dst[(size_t)(b * NH + j) * HID + i0 + i]     = v0;
            *(float2*)&dst[(size_t)(b * NH + j + 8) * HID + i0 + i] = v1;
        }
    }
}

// ---------------------------------------------------------------------------
// 6) mid, split-K x4 with atomic epilogue; sums the 2 agg partials
__global__ void k_mid(const float* __restrict__ Wv) {
    __shared__ float As[8][65];
    __shared__ float Bs[64][65];
    int h = blockIdx.x, b = blockIdx.y, kc = blockIdx.z;
    int tid = threadIdx.x;
    float acc0 = 0.f, acc1 = 0.f;
    int o0 = tid, o1 = tid + 256;
    int n0 = o0 >> 6, d0 = o0 & 63;
    int n1 = o1 >> 6, d1 = o1 & 63;
    int k0 = kc * (HID / 4), k1 = k0 + HID / 4;
    for (int kt = k0; kt < k1; kt += 64) {
        {
            int e = tid; int r = e >> 6, c = e & 63;
            size_t ix = (size_t)(b * NH + h * SLOTS + r) * HID + kt + c;
            As[r][c] = g_apart[ix] + g_apart[APART_SZ + ix];
            e = tid + 256; r = e >> 6; c = e & 63;
            ix = (size_t)(b * NH + h * SLOTS + r) * HID + kt + c;
            As[r][c] = g_apart[ix] + g_apart[APART_SZ + ix];
        }
        #pragma unroll
        for (int l = 0; l < 16; l++) {
            int e = tid + l * 256;
            int r = e >> 6, c = e & 63;
            Bs[r][c] = Wv[(h * HD + r) * HID + kt + c];
        }
        __syncthreads();
        #pragma unroll
        for (int k = 0; k < 64; k++) {
            acc0 += As[n0][k] * Bs[d0][k];
            acc1 += As[n1][k] * Bs[d1][k];
        }
        __syncthreads();
    }
    atomicAdd(&g_mid[(b * SLOTS + n0) * BD + h * HD + d0], acc0);
    atomicAdd(&g_mid[(b * SLOTS + n1) * BD + h * HD + d1], acc1);
}

// ---------------------------------------------------------------------------
// 7) final, o-tile 64
__global__ void k_final(const float* __restrict__ Wo, float* __restrict__ out) {
    __shared__ float As[32][65];
    __shared__ float Bs[64][65];
    int tid = threadIdx.x;
    int tx = tid & 15, ty = tid >> 4;
    int o0 = blockIdx.x * 64;
    float acc[2][4] = {};
    for (int kt = 0; kt < BD; kt += 64) {
        #pragma unroll
        for (int l = 0; l < 8; l++) {
            int e = tid + l * 256;
            int r = e >> 6, c = e & 63;
            As[r][c] = g_mid[r * BD + kt + c];
        }
        #pragma unroll
        for (int l = 0; l < 16; l++) {
            int e = tid + l * 256;
            int r = e >> 6, c = e & 63;
            Bs[r][c] = Wo[(o0 + r) * BD + kt + c];
        }
        __syncthreads();
        #pragma unroll
        for (int k = 0; k < 64; k++) {
            float a[2], bb[4];
            #pragma unroll
            for (int x = 0; x < 2; x++) a[x] = As[ty * 2 + x][k];
            #pragma unroll
            for (int y = 0; y < 4; y++) bb[y] = Bs[tx * 4 + y][k];
            #pragma unroll
            for (int x = 0; x < 2; x++)
                #pragma unroll
                for (int y = 0; y < 4; y++) acc[x][y] += a[x] * bb[y];
        }
        __syncthreads();
    }
    #pragma unroll
    for (int x = 0; x < 2; x++)
        #pragma unroll
        for (int y = 0; y < 4; y++)
            out[(ty * 2 + x) * HID + o0 + tx * 4 + y] = acc[x][y];
}

// ---------------------------------------------------------------------------
extern "C" void kernel_launch(void* const* d_in, const int* in_sizes, int n_in,
                              void* d_out, int out_size) {
    const float* H    = (const float*)d_in[0];
    const int*   mask = (const int*)d_in[1];
    const float* ms   = (const float*)d_in[2];
    const float* Wq   = (const float*)d_in[3];
    const float* Wk   = (const float*)d_in[4];
    const float* Wv   = (const float*)d_in[5];
    const float* Wo   = (const float*)d_in[6];
    float* out = (float*)d_out;

    static int attr_done = 0;
    if (!attr_done) {
        cudaFuncSetAttribute(k_scores, cudaFuncAttributeMaxDynamicSharedMemorySize,
                             2 * S_STAGE * 4);
        cudaFuncSetAttribute(k_agg, cudaFuncAttributeMaxDynamicSharedMemorySize,
                             2 * G_STAGE * 4);
        attr_done = 1;
    }

    k_compact<<<BB, 256>>>(mask);
    k_qproj <<<512, 256>>>(ms, Wq);
    k_qk    <<<dim3(HID / 256, NH), 256>>>(Wk);
    k_scores<<<dim3(SS / 64, BB, 4), 256, 2 * S_STAGE * 4>>>(H);
    k_softmax<<<BB * NH, 256>>>();
    k_agg   <<<dim3(HID / 64, BB, 2), 256, 2 * G_STAGE * 4>>>(H);
    k_mid   <<<dim3(HEADS, BB, 4), 256>>>(Wv);
    k_final <<<HID / 64, 256>>>(Wo, out);
}